// round 9
// baseline (speedup 1.0000x reference)
#include <cuda_runtime.h>

#define N_   8
#define C_   4
#define H_   64
#define W_   64
#define F_   16
#define KK   5
#define HO   60
#define WO   60
#define NTAPS (KK*KK*C_)     // 100

typedef unsigned long long u64;

__device__ __forceinline__ u64 ffma2(u64 a, u64 b, u64 c) {
    u64 d; asm("fma.rn.f32x2 %0, %1, %2, %3;" : "=l"(d) : "l"(a), "l"(b), "l"(c)); return d;
}
__device__ __forceinline__ u64 dup2(float x) {
    u64 d; asm("mov.b64 %0, {%1, %1};" : "=l"(d) : "f"(x)); return d;
}
__device__ __forceinline__ float2 unpk2(u64 v) {
    float2 r; asm("mov.b64 {%0, %1}, %2;" : "=f"(r.x), "=f"(r.y) : "l"(v)); return r;
}

// Block = (ho, n, filter-half). 960 blocks of 128 threads: finer work grains
// even out the 148-SM wave (tail 1.08 vs 1.24) and smem drops to ~33KB so
// ~6 blocks/SM stay resident (occ ~40%).
// blockDim (64,2): x = wo lane (60 active), y = fg; thread computes 1 pixel
// for 4 filters (2 f32x2 pairs) out of this block's 8-filter half.
__global__ __launch_bounds__(128) void smorph_fused_kernel(
    const float* __restrict__ x, const float* __restrict__ k1,
    const float* __restrict__ k2, const float* __restrict__ bias,
    float* __restrict__ out)
{
    // sw per tap: 32 floats = [fg(2)][ w0[4] w1[4] w2[4] w3[4] ]
    __shared__ __align__(16) float  sw[NTAPS * 32];   // 12800 B
    __shared__ float4 sin_[C_][KK][W_];               // 20480 B

    const int ho    = blockIdx.x;
    const int n     = blockIdx.y;
    const int fgblk = blockIdx.z;        // filters fgblk*8 .. fgblk*8+7
    const int tid   = threadIdx.y * 64 + threadIdx.x;

    // ---- Phase 1: weight transform for this block's 8 filters ----
    #pragma unroll
    for (int i = tid; i < NTAPS * 8; i += 128) {
        int tap = i >> 3;
        int f8  = i & 7;                      // 0..7 within half
        int ki  = tap * F_ + fgblk * 8 + f8;  // index into k1/k2
        float v1 = k1[ki], v2 = k2[ki];
        float e1 = __expf(v1), e2 = __expf(v2);
        float* p = sw + tap * 32 + (f8 >> 2) * 16 + (f8 & 3);
        p[0]  = e1;
        p[4]  = v1 * e1;
        p[8]  = e2;
        p[12] = v2 * e2;
    }

    // ---- Phase 2: input transform for rows ho..ho+4, all channels ----
    const float* gx = x + (size_t)n * C_ * H_ * W_;
    float4* sflat = &sin_[0][0][0];
    #pragma unroll
    for (int i = tid; i < C_ * KK * W_; i += 128) {
        int w  = i & (W_ - 1);
        int r  = i >> 6;            // c*KK + dh
        int c  = r / KK;
        int dh = r - c * KK;
        float xv = gx[(c * H_ + ho + dh) * W_ + w];
        float e  = __expf(xv);
        float en = __expf(-xv);
        sflat[i] = make_float4(e, xv * e, en, -xv * en);
    }
    __syncthreads();

    const int wo = threadIdx.x;
    const int fg = threadIdx.y;          // pair-group within the half
    if (wo >= WO) return;

    u64 acc0[2] = {0,0};   // sum a * ek1
    u64 acc1[2] = {0,0};   // sum a*wk1 + b*ek1
    u64 acc2[2] = {0,0};   // sum a' * ek2
    u64 acc3[2] = {0,0};   // sum a'*wk2 + b'*ek2

    const float4* swbase = (const float4*)sw + fg * 4;   // 8 float4 per tap

    #pragma unroll 1
    for (int kh = 0; kh < KK; kh++) {
        #pragma unroll
        for (int kw = 0; kw < KK; kw++) {
            #pragma unroll
            for (int c = 0; c < C_; c++) {
                const int tap = (kh * KK + kw) * C_ + c;
                const float4* wp4 = swbase + tap * 8;
                float4 w0 = wp4[0];
                float4 w1 = wp4[1];
                float4 w2 = wp4[2];
                float4 w3 = wp4[3];
                const u64* w0u = (const u64*)&w0;
                const u64* w1u = (const u64*)&w1;
                const u64* w2u = (const u64*)&w2;
                const u64* w3u = (const u64*)&w3;

                float4 in = sin_[c][kh][wo + kw];
                u64 ax = dup2(in.x), bx = dup2(in.y);
                u64 az = dup2(in.z), bw = dup2(in.w);

                #pragma unroll
                for (int j = 0; j < 2; j++) {
                    acc0[j] = ffma2(ax, w0u[j], acc0[j]);
                    acc1[j] = ffma2(ax, w1u[j], ffma2(bx, w0u[j], acc1[j]));
                    acc2[j] = ffma2(az, w2u[j], acc2[j]);
                    acc3[j] = ffma2(az, w3u[j], ffma2(bw, w2u[j], acc3[j]));
                }
            }
        }
    }

    // Epilogue: y = num1/den1 + num2/den2 + bias (denominators strictly > 0)
    const int fbase = fgblk * 8 + fg * 4;
    float* op = out + (((size_t)n * F_ + fbase) * HO + ho) * WO + wo;
    #pragma unroll
    for (int j = 0; j < 2; j++) {
        float2 d1 = unpk2(acc0[j]);
        float2 n1 = unpk2(acc1[j]);
        float2 d2 = unpk2(acc2[j]);
        float2 n2 = unpk2(acc3[j]);
        int f = 2 * j;
        float y0 = __fdividef(n1.x, d1.x) + __fdividef(n2.x, d2.x) + bias[fbase + f];
        float y1 = __fdividef(n1.y, d1.y) + __fdividef(n2.y, d2.y) + bias[fbase + f + 1];
        op[(size_t)f       * HO * WO] = y0;
        op[(size_t)(f + 1) * HO * WO] = y1;
    }
}

extern "C" void kernel_launch(void* const* d_in, const int* in_sizes, int n_in,
                              void* d_out, int out_size) {
    const float* x    = (const float*)d_in[0];
    const float* k1   = (const float*)d_in[1];
    const float* k2   = (const float*)d_in[2];
    const float* bias = (const float*)d_in[3];
    float* out = (float*)d_out;

    dim3 grid(HO, N_, 2);
    dim3 block(64, 2);
    smorph_fused_kernel<<<grid, block>>>(x, k1, k2, bias, out);
}

// round 12
// speedup vs baseline: 1.0932x; 1.0932x over previous
#include <cuda_runtime.h>

#define N_   8
#define C_   4
#define H_   64
#define W_   64
#define F_   16
#define KK   5
#define HO   60
#define WO   60
#define NTAPS (KK*KK*C_)     // 100
#define NROWS 6              // input rows per block (2 output rows)

typedef unsigned long long u64;

__device__ __forceinline__ u64 ffma2(u64 a, u64 b, u64 c) {
    u64 d; asm("fma.rn.f32x2 %0, %1, %2, %3;" : "=l"(d) : "l"(a), "l"(b), "l"(c)); return d;
}
__device__ __forceinline__ u64 dup2(float x) {
    u64 d; asm("mov.b64 %0, {%1, %1};" : "=l"(d) : "f"(x)); return d;
}
__device__ __forceinline__ float2 unpk2(u64 v) {
    float2 r; asm("mov.b64 {%0, %1}, %2;" : "=f"(r.x), "=f"(r.y) : "l"(v)); return r;
}

// Block = (2 ho rows, n, 8-filter half). blockDim (16,2,2)=64:
// tx = pixel base (4 px/thread: tx, tx+16, tx+32, tx+48), ty = fg (4 filters
// as 2 f32x2 pairs), tz = which of the 2 ho rows.
// Rationale: the smem crossbar is byte-bound with NO broadcast dedup
// (uniform LDS.128 = 4 cyc). 4 px/thread amortizes the broadcast weight
// bytes: LSU cyc per output-tap 0.156 -> 0.0625 (floor 27 -> ~11us).
__global__ __launch_bounds__(64) void smorph_fused_kernel(
    const float* __restrict__ x, const float* __restrict__ k1,
    const float* __restrict__ k2, const float* __restrict__ bias,
    float* __restrict__ out)
{
    // sw per tap: 32 floats = [fg(2)][ w0[4] w1[4] w2[4] w3[4] ]
    __shared__ __align__(16) float  sw[NTAPS * 32];     // 12800 B
    __shared__ float4 sin_[C_][NROWS][W_];              // 24576 B

    const int hob   = blockIdx.x * 2;
    const int n     = blockIdx.y;
    const int fhalf = blockIdx.z;        // filters fhalf*8 .. +7
    const int tx  = threadIdx.x;         // 0..15
    const int ty  = threadIdx.y;         // 0..1
    const int tz  = threadIdx.z;         // 0..1
    const int tid = (tz * 2 + ty) * 16 + tx;   // 0..63

    // ---- Phase 1: weight transform for this block's 8 filters ----
    #pragma unroll
    for (int i = tid; i < NTAPS * 8; i += 64) {
        int tap = i >> 3;
        int f8  = i & 7;
        int ki  = tap * F_ + fhalf * 8 + f8;
        float v1 = k1[ki], v2 = k2[ki];
        float e1 = __expf(v1), e2 = __expf(v2);
        float* p = sw + tap * 32 + (f8 >> 2) * 16 + (f8 & 3);
        p[0]  = e1;
        p[4]  = v1 * e1;
        p[8]  = e2;
        p[12] = v2 * e2;
    }

    // ---- Phase 2: input transform, rows hob..hob+5, all channels ----
    const float* gx = x + (size_t)n * C_ * H_ * W_;
    float4* sflat = &sin_[0][0][0];
    #pragma unroll
    for (int i = tid; i < C_ * NROWS * W_; i += 64) {
        int w  = i & (W_ - 1);
        int r  = i >> 6;            // c*NROWS + dh
        int c  = r / NROWS;
        int dh = r - c * NROWS;
        float xv = gx[(c * H_ + hob + dh) * W_ + w];
        float e  = __expf(xv);
        float en = __expf(-xv);
        sflat[i] = make_float4(e, xv * e, en, -xv * en);
    }
    __syncthreads();

    // Pixel positions (p=3 clamped for tx>=12; store masked)
    const int wo3 = (tx + 48 < WO) ? (tx + 48) : (WO - 1);
    const int wop[4] = { tx, tx + 16, tx + 32, wo3 };

    // acc[type][px][pair]
    u64 acc0[4][2] = {}, acc1[4][2] = {}, acc2[4][2] = {}, acc3[4][2] = {};

    const float4* swbase = (const float4*)sw + ty * 4;   // 8 float4 per tap

    #pragma unroll 1
    for (int kh = 0; kh < KK; kh++) {
        const float4* rowbase[C_];
        #pragma unroll
        for (int c = 0; c < C_; c++) rowbase[c] = &sin_[c][tz + kh][0];
        #pragma unroll
        for (int kw = 0; kw < KK; kw++) {
            #pragma unroll
            for (int c = 0; c < C_; c++) {
                const int tap = (kh * KK + kw) * C_ + c;
                const float4* wp4 = swbase + tap * 8;
                float4 w0 = wp4[0];
                float4 w1 = wp4[1];
                float4 w2 = wp4[2];
                float4 w3 = wp4[3];
                const u64* w0u = (const u64*)&w0;
                const u64* w1u = (const u64*)&w1;
                const u64* w2u = (const u64*)&w2;
                const u64* w3u = (const u64*)&w3;

                #pragma unroll
                for (int p = 0; p < 4; p++) {
                    float4 in = rowbase[c][wop[p] + kw];
                    u64 ax = dup2(in.x), bx = dup2(in.y);
                    u64 az = dup2(in.z), bw = dup2(in.w);
                    #pragma unroll
                    for (int j = 0; j < 2; j++) {
                        acc0[p][j] = ffma2(ax, w0u[j], acc0[p][j]);
                        acc1[p][j] = ffma2(ax, w1u[j], ffma2(bx, w0u[j], acc1[p][j]));
                        acc2[p][j] = ffma2(az, w2u[j], acc2[p][j]);
                        acc3[p][j] = ffma2(az, w3u[j], ffma2(bw, w2u[j], acc3[p][j]));
                    }
                }
            }
        }
    }

    // Epilogue: y = num1/den1 + num2/den2 + bias (denominators strictly > 0)
    const int ho    = hob + tz;
    const int fbase = fhalf * 8 + ty * 4;
    #pragma unroll
    for (int p = 0; p < 4; p++) {
        int wo = tx + 16 * p;
        if (wo >= WO) break;                    // only p=3 for tx>=12
        float* op = out + (((size_t)n * F_ + fbase) * HO + ho) * WO + wo;
        #pragma unroll
        for (int j = 0; j < 2; j++) {
            float2 d1 = unpk2(acc0[p][j]);
            float2 n1 = unpk2(acc1[p][j]);
            float2 d2 = unpk2(acc2[p][j]);
            float2 n2 = unpk2(acc3[p][j]);
            int f = 2 * j;
            float y0 = __fdividef(n1.x, d1.x) + __fdividef(n2.x, d2.x) + bias[fbase + f];
            float y1 = __fdividef(n1.y, d1.y) + __fdividef(n2.y, d2.y) + bias[fbase + f + 1];
            op[(size_t)f       * HO * WO] = y0;
            op[(size_t)(f + 1) * HO * WO] = y1;
        }
    }
}

extern "C" void kernel_launch(void* const* d_in, const int* in_sizes, int n_in,
                              void* d_out, int out_size) {
    const float* x    = (const float*)d_in[0];
    const float* k1   = (const float*)d_in[1];
    const float* k2   = (const float*)d_in[2];
    const float* bias = (const float*)d_in[3];
    float* out = (float*)d_out;

    dim3 grid(HO / 2, N_, 2);
    dim3 block(16, 2, 2);
    smorph_fused_kernel<<<grid, block>>>(x, k1, k2, bias, out);
}